// round 13
// baseline (speedup 1.0000x reference)
#include <cuda_runtime.h>
#include <cuda_fp16.h>
#include <math.h>
#include <stdint.h>

#define BATCH 4
#define SEQ   2048
#define DIM   1024
#define NH    16
#define HD    64
#define MTOK  (BATCH*SEQ)        // 8192
#define SCALE_LOG2E 0.1803368801111204f   // (1/sqrt(64)) * log2(e)

// Scratch (allocation-free: __device__ globals), all fp16
__device__ __half g_xh[MTOK*DIM];          // fp16 copy of x
__device__ __half g_wqkvT[3*DIM*DIM];      // [3072][1024] = w_qkv^T
__device__ __half g_woutT[DIM*DIM];        // [1024][1024] = w_out^T
__device__ __half g_q[BATCH*NH*SEQ*HD];    // (B,H,S,Hd), pre-scaled by log2e/8
__device__ __half g_k[BATCH*NH*SEQ*HD];
__device__ __half g_v[BATCH*NH*SEQ*HD];
__device__ __half g_attn[MTOK*DIM];        // (B*S, D)

// ---------------------------------------------------------------------------
// helpers
// ---------------------------------------------------------------------------
__device__ __forceinline__ uint32_t f2h2(float lo, float hi) {
    __half2 h = __floats2half2_rn(lo, hi);
    return *reinterpret_cast<uint32_t*>(&h);
}

__device__ __forceinline__ float ex2f(float x) {
    float r;
    asm("ex2.approx.f32 %0, %1;" : "=f"(r) : "f"(x));
    return r;
}

__device__ __forceinline__ uint32_t smem_u32(const void* p) {
    uint32_t a;
    asm("{ .reg .u64 t; cvta.to.shared.u64 t, %1; cvt.u32.u64 %0, t; }"
        : "=r"(a) : "l"(p));
    return a;
}

__device__ __forceinline__ void mma_f16(float c[4],
                                        const uint32_t a[4],
                                        const uint32_t b[2]) {
    asm volatile(
        "mma.sync.aligned.m16n8k16.row.col.f32.f16.f16.f32 "
        "{%0,%1,%2,%3},{%4,%5,%6,%7},{%8,%9},{%0,%1,%2,%3};"
        : "+f"(c[0]), "+f"(c[1]), "+f"(c[2]), "+f"(c[3])
        : "r"(a[0]), "r"(a[1]), "r"(a[2]), "r"(a[3]),
          "r"(b[0]), "r"(b[1]));
}

#define LDSM4(r0, r1, r2, r3, addr) \
    asm volatile("ldmatrix.sync.aligned.m8n8.x4.shared.b16 {%0,%1,%2,%3},[%4];" \
        : "=r"(r0), "=r"(r1), "=r"(r2), "=r"(r3) : "r"(addr))

#define LDSM4T(r0, r1, r2, r3, addr) \
    asm volatile("ldmatrix.sync.aligned.m8n8.x4.trans.shared.b16 {%0,%1,%2,%3},[%4];" \
        : "=r"(r0), "=r"(r1), "=r"(r2), "=r"(r3) : "r"(addr))

#define CPA16(saddr, gptr) \
    asm volatile("cp.async.cg.shared.global [%0], [%1], 16;" \
        :: "r"(saddr), "l"(gptr) : "memory")
#define CP_COMMIT() asm volatile("cp.async.commit_group;" ::: "memory")
#define CP_WAIT1()  asm volatile("cp.async.wait_group 1;" ::: "memory")
#define CP_WAIT0()  asm volatile("cp.async.wait_group 0;" ::: "memory")

// ---------------------------------------------------------------------------
// prep kernels
// ---------------------------------------------------------------------------
__global__ void xcvt(const float* __restrict__ x, __half* __restrict__ dst)
{
    int i = blockIdx.x * blockDim.x + threadIdx.x;   // over float4s
    float4 v = ((const float4*)x)[i];
    uint2 u;
    u.x = f2h2(v.x, v.y);
    u.y = f2h2(v.z, v.w);
    ((uint2*)dst)[i] = u;
}

__global__ void wtrans(const float* __restrict__ src, __half* __restrict__ dst,
                       int K, int N)
{
    __shared__ float sm[32][33];
    int tx = threadIdx.x, ty = threadIdx.y;
    int n0 = blockIdx.x * 32, k0 = blockIdx.y * 32;
    #pragma unroll
    for (int j = 0; j < 32; j += 8)
        sm[ty + j][tx] = src[(size_t)(k0 + ty + j)*N + n0 + tx];
    __syncthreads();
    #pragma unroll
    for (int j = 0; j < 32; j += 8)
        dst[(size_t)(n0 + ty + j)*K + k0 + tx] = __float2half(sm[tx][ty + j]);
}

// ---------------------------------------------------------------------------
// fp16 MMA GEMM: BK=64 halves per k-block, 3-stage cp.async ring, ONE
// __syncthreads per k-block (16 total). 128x128 block, 256 threads = 8 warps
// (2x4), warp tile 64x32. SMEM [row][k-word] pitch 36 (conflict-free LDSM).
// ---------------------------------------------------------------------------
#define KPW 36
#define NKB (DIM/64)            // 16
#define GSTG 3
#define STGB (128*KPW*4)        // 18432 B per stage per operand
#define GEMM_SMEM (2*GSTG*STGB) // 110592

__device__ __forceinline__ void comp16(uint32_t Aln, uint32_t Bln,
                                       float acc[4][4][4]) {
    #pragma unroll
    for (int st = 0; st < 4; st++) {
        uint32_t af[4][4], bf[4][2];
        #pragma unroll
        for (int mt = 0; mt < 4; mt++)
            LDSM4(af[mt][0], af[mt][1], af[mt][2], af[mt][3],
                  Aln + (mt*16*KPW + st*8)*4);
        #pragma unroll
        for (int ntp = 0; ntp < 2; ntp++)
            LDSM4(bf[2*ntp][0], bf[2*ntp][1], bf[2*ntp+1][0], bf[2*ntp+1][1],
                  Bln + (ntp*16*KPW + st*8)*4);
        #pragma unroll
        for (int mt = 0; mt < 4; mt++)
            #pragma unroll
            for (int nt = 0; nt < 4; nt++)
                mma_f16(acc[mt][nt], af[mt], bf[nt]);
    }
}

// 3-stage BK=64 mainloop. Thread stages row r, half-range h (32 halves).
#define GEMM_PIPE(aRow, bRow)                                                  \
    extern __shared__ uint32_t dsm[];                                          \
    uint32_t aBase = smem_u32(dsm);                                            \
    uint32_t bBase = aBase + GSTG*STGB;                                        \
    uint32_t sA0 = aBase + (r*KPW + 16*h)*4;                                   \
    uint32_t sB0 = bBase + (r*KPW + 16*h)*4;                                   \
    uint32_t Aln0 = aBase + (((wr*64 + (mid&1)*8 + l7)*KPW) + (mid>>1)*4)*4;   \
    uint32_t Bln0 = bBase + (((wc*32 + (mid>>1)*8 + l7)*KPW) + (mid&1)*4)*4;   \
    _Pragma("unroll")                                                          \
    for (int s = 0; s < GSTG-1; s++) {                                         \
        const __half* ga = (aRow) + s*64;                                      \
        const __half* gb = (bRow) + s*64;                                      \
        _Pragma("unroll")                                                      \
        for (int c = 0; c < 4; c++) {                                          \
            CPA16(sA0 + s*STGB + c*16, ga + c*8);                              \
            CPA16(sB0 + s*STGB + c*16, gb + c*8);                              \
        }                                                                      \
        CP_COMMIT();                                                           \
    }                                                                          \
    for (int kb = 0; kb < NKB; kb++) {                                         \
        if (kb + 1 < NKB) CP_WAIT1();                                          \
        else              CP_WAIT0();                                          \
        __syncthreads();                                                       \
        int sl = kb % GSTG;                                                    \
        int nk = kb + GSTG - 1;                                                \
        if (nk < NKB) {                                                        \
            int ps = nk % GSTG;                                                \
            const __half* ga = (aRow) + nk*64;                                 \
            const __half* gb = (bRow) + nk*64;                                 \
            _Pragma("unroll")                                                  \
            for (int c = 0; c < 4; c++) {                                      \
                CPA16(sA0 + ps*STGB + c*16, ga + c*8);                         \
                CPA16(sB0 + ps*STGB + c*16, gb + c*8);                         \
            }                                                                  \
            CP_COMMIT();                                                       \
        }                                                                      \
        comp16(Aln0 + sl*STGB, Bln0 + sl*STGB, acc);                           \
    }

// ---- qkv GEMM: xh(fp16) @ wqkvT(fp16) + bias -> scatter g_q/g_k/g_v (fp16)
__global__ void __launch_bounds__(256) gemm_qkv(const float* __restrict__ bias)
{
    int tid = threadIdx.x, lane = tid & 31, wid = tid >> 5;
    int wr = wid >> 2, wc = wid & 3, gid = lane >> 2, q4 = lane & 3;
    int row0 = blockIdx.y * 128, col0 = blockIdx.x * 128;
    int r = tid >> 1, h = tid & 1;
    int mid = lane >> 3, l7 = lane & 7;

    float acc[4][4][4];
    #pragma unroll
    for (int mt = 0; mt < 4; mt++)
        #pragma unroll
        for (int nt = 0; nt < 4; nt++)
            #pragma unroll
            for (int e = 0; e < 4; e++) acc[mt][nt][e] = 0.f;

    const __half* aRow = g_xh    + (size_t)(row0 + r)*DIM + 32*h;
    const __half* bRow = g_wqkvT + (size_t)(col0 + r)*DIM + 32*h;

    GEMM_PIPE(aRow, bRow)

    // epilogue: +bias, scatter as half2
    #pragma unroll
    for (int mt = 0; mt < 4; mt++) {
        #pragma unroll
        for (int nt = 0; nt < 4; nt++) {
            int col = col0 + wc*32 + nt*8 + 2*q4;
            float2 bs = *(const float2*)&bias[col];
            int three = col >> 10;
            int rem   = col & 1023;
            int hh    = rem >> 6;
            int hd    = rem & 63;
            float sc = (three == 0) ? SCALE_LOG2E : 1.f;
            __half* dstb = (three == 0) ? g_q : (three == 1) ? g_k : g_v;
            #pragma unroll
            for (int half_i = 0; half_i < 2; half_i++) {
                int row = row0 + wr*64 + mt*16 + gid + half_i*8;
                int b  = row >> 11;
                int s  = row & 2047;
                float v0 = (acc[mt][nt][2*half_i]   + bs.x) * sc;
                float v1 = (acc[mt][nt][2*half_i+1] + bs.y) * sc;
                size_t dst = ((size_t)(b*NH + hh)*SEQ + s)*HD + hd;
                *(uint32_t*)&dstb[dst] = f2h2(v0, v1);
            }
        }
    }
}

// ---- out GEMM: g_attn(fp16) @ woutT(fp16) + bias -> d_out (fp32)
__global__ void __launch_bounds__(256) gemm_out(
    const float* __restrict__ bias, float* __restrict__ C)
{
    int tid = threadIdx.x, lane = tid & 31, wid = tid >> 5;
    int wr = wid >> 2, wc = wid & 3, gid = lane >> 2, q4 = lane & 3;
    int row0 = blockIdx.y * 128, col0 = blockIdx.x * 128;
    int r = tid >> 1, h = tid & 1;
    int mid = lane >> 3, l7 = lane & 7;

    float acc[4][4][4];
    #pragma unroll
    for (int mt = 0; mt < 4; mt++)
        #pragma unroll
        for (int nt = 0; nt < 4; nt++)
            #pragma unroll
            for (int e = 0; e < 4; e++) acc[mt][nt][e] = 0.f;

    const __half* aRow = g_attn  + (size_t)(row0 + r)*DIM + 32*h;
    const __half* bRow = g_woutT + (size_t)(col0 + r)*DIM + 32*h;

    GEMM_PIPE(aRow, bRow)

    #pragma unroll
    for (int mt = 0; mt < 4; mt++) {
        #pragma unroll
        for (int nt = 0; nt < 4; nt++) {
            int col = col0 + wc*32 + nt*8 + 2*q4;
            float2 bs = *(const float2*)&bias[col];
            #pragma unroll
            for (int half_i = 0; half_i < 2; half_i++) {
                int row = row0 + wr*64 + mt*16 + gid + half_i*8;
                float2 v;
                v.x = acc[mt][nt][2*half_i]   + bs.x;
                v.y = acc[mt][nt][2*half_i+1] + bs.y;
                *(float2*)&C[(size_t)row*DIM + col] = v;
            }
        }
    }
}

// ---------------------------------------------------------------------------
// Fused flash attention: fp16 m16n8k16, register-resident P, ldmatrix loads,
// 3-stage cp.async ring for K/V tiles. (unchanged from round 12)
// ---------------------------------------------------------------------------
#define QT 128
#define KT 64
#define PW 36
#define ASTG 3
#define KVSTGB (KT*PW*4)
#define ATT_SMEM_WORDS ((QT + 2*ASTG*KT) * PW)   // 18432 words = 73728 B

__global__ void __launch_bounds__(128, 3) attn_kernel()
{
    extern __shared__ uint32_t smu[];
    uint32_t (*Qs)[PW] = (uint32_t (*)[PW])smu;      // [128 q][32 dw]
    uint32_t kBase = smem_u32(smu + QT*PW);          // K: 3 stages
    uint32_t vBase = kBase + ASTG*KVSTGB;            // V: 3 stages

    int tid  = threadIdx.x;
    int lane = tid & 31;
    int w    = tid >> 5;
    int mid  = lane >> 3, l7 = lane & 7;

    int b  = blockIdx.z;
    int h  = blockIdx.y;
    int q0 = blockIdx.x * QT;

    const __half* qptr = g_q + ((size_t)(b*NH + h)*SEQ)*HD;
    const __half* kptr = g_k + ((size_t)(b*NH + h)*SEQ)*HD;
    const __half* vptr = g_v + ((size_t)(b*NH + h)*SEQ)*HD;

    int sr = tid >> 3;          // 0..15
    int scu = tid & 7;          // 0..7
    uint32_t sK0 = kBase + (sr*PW + scu*4)*4;
    uint32_t sV0 = vBase + (sr*PW + scu*4)*4;

    uint32_t Qln = smem_u32(Qs) + (((w*32 + (mid&1)*8 + l7)*PW) + (mid>>1)*4)*4;
    uint32_t Kln = kBase + ((((mid>>1)*8 + l7)*PW) + (mid&1)*4)*4;
    uint32_t Vln = vBase + ((((mid&1)*8 + l7)*PW) + (mid>>1)*4)*4;

    // load Q tile (128x64 halves) via uint4 copies
    #pragma unroll
    for (int it = 0; it < 8; it++) {
        int u  = tid + it*128;
        int r  = u >> 3;
        int cu = u & 7;
        uint4 v = *(const uint4*)&qptr[(size_t)(q0 + r)*HD + cu*8];
        *(uint4*)&Qs[r][cu*4] = v;
    }

    // prefetch K/V tiles 0,1 into stages 0,1
    #pragma unroll
    for (int s = 0; s < ASTG-1; s++) {
        #pragma unroll
        for (int it = 0; it < 4; it++) {
            int r = s*KT + sr + it*16;
            CPA16(sK0 + s*KVSTGB + it*16*PW*4, &kptr[(size_t)r*HD + scu*8]);
            CPA16(sV0 + s*KVSTGB + it*16*PW*4, &vptr[(size_t)r*HD + scu*8]);
        }
        CP_COMMIT();
    }

    float m_a[2], m_b[2], l_a[2], l_b[2];
    float O[2][8][4];
    #pragma unroll
    for (int mt = 0; mt < 2; mt++) {
        m_a[mt] = -INFINITY; m_b[mt] = -INFINITY;
        l_a[mt] = 0.f; l_b[mt] = 0.f;
        #pragma unroll
        for (int dt = 0; dt < 8; dt++)
            #pragma unroll
            for (int e = 0; e < 4; e++) O[mt][dt][e] = 0.f;
    }

    const int NTI = SEQ/KT;   // 32
    for (int ti = 0; ti < NTI; ti++) {
        if (ti + 1 < NTI) CP_WAIT1();
        else              CP_WAIT0();
        __syncthreads();

        int sl = ti % ASTG;
        uint32_t Klb = Kln + sl*KVSTGB;
        uint32_t Vlb = Vln + sl*KVSTGB;

        // S = Q @ K^T
        float S[2][8][4];
        #pragma unroll
        for (int mt = 0; mt < 2; mt++)
            #pragma unroll
            for (int nt = 0; nt < 8; nt++)
                #pragma unroll
                for (int e = 0; e < 4; e++) S[mt][nt][e] = 0.f;

        #pragma unroll
        for (int kk = 0; kk < 4; kk++) {
            uint32_t bf[8][2];
            #pragma unroll
            for (int ntp = 0; ntp < 4; ntp++)
                LDSM4(bf[2*ntp][0], bf[2*ntp][1], bf[2*ntp+1][0], bf[2*ntp+1][1],
                      Klb + (ntp*16*PW + kk*8)*4);
            #pragma unroll
            for (int mt = 0; mt < 2; mt++) {
                uint32_t qf[4];
                LDSM4(qf[0], qf[1], qf[2], qf[3],
                      Qln + (mt*16*PW + kk*8)*4);
                #pragma unroll
                for (int nt = 0; nt < 8; nt++)
                    mma_f16(S[mt][nt], qf, bf[nt]);
            }
        }

        // prefetch tile ti+2
        int nt2 = ti + ASTG - 1;
        if (nt2 < NTI) {
            int ps = nt2 % ASTG;
            #pragma unroll
            for (int it = 0; it < 4; it++) {
                int r = nt2*KT + sr + it*16;
                CPA16(sK0 + ps*KVSTGB + it*16*PW*4, &kptr[(size_t)r*HD + scu*8]);
                CPA16(sV0 + ps*KVSTGB + it*16*PW*4, &vptr[(size_t)r*HD + scu*8]);
            }
            CP_COMMIT();
        }

        // online softmax (exp2 domain)
        #pragma unroll
        for (int mt = 0; mt < 2; mt++) {
            float ma = S[mt][0][0], mb = S[mt][0][2];
            #pragma unroll
            for (int nt = 0; nt < 8; nt++) {
                ma = fmaxf(ma, fmaxf(S[mt][nt][0], S[mt][nt][1]));
                mb = fmaxf(mb, fmaxf(S[mt][nt][2], S[mt][nt][3]));
            }
            #pragma unroll
            for (int off = 1; off <= 2; off <<= 1) {
                ma = fmaxf(ma, __shfl_xor_sync(0xffffffffu, ma, off));
                mb = fmaxf(mb, __shfl_xor_sync(0xffffffffu, mb, off));
            }
            float mna = fmaxf(m_a[mt], ma);
            float mnb = fmaxf(m_b[mt], mb);
            float alpha_a = ex2f(m_a[mt] - mna);
            float alpha_b = ex2f(m_b[mt] - mnb);
            float sa = 0.f, sb = 0.f;
            #pragma unroll
            for (int nt = 0; nt < 8; nt++) {
                S[mt][nt][0] = ex2f(S[mt][nt][0] - mna);
                S[mt][nt][1] = ex2f(S[mt][nt][1] - mna);
                S[mt][nt][2] = ex2f(S[mt][nt][2] - mnb);
                S[mt][nt][3] = ex2f(S[mt][nt][3] - mnb);
                sa += S[mt][nt][0] + S[mt][nt][1];
                sb += S[mt][nt][2] + S[mt][nt][3];
            }
            #pragma unroll
            for (int off = 1; off <= 2; off <<= 1) {
                sa += __shfl_xor_sync(0xffffffffu, sa, off);
                sb += __shfl_xor_sync(0xffffffffu, sb, off);
            }
            l_a[mt] = l_a[mt] * alpha_a + sa;
            l_b[mt] = l_b[mt] * alpha_b + sb;
            m_a[mt] = mna; m_b[mt] = mnb;
            #pragma unroll
            for (int dt = 0; dt < 8; dt++) {
                O[mt][dt][0] *= alpha_a; O[mt][dt][1] *= alpha_a;
                O[mt][dt][2] *= alpha_b; O[mt][dt][3] *= alpha_b;
            }
        }

        // O += P @ V (register P, ldmatrix.trans V)
        #pragma unroll
        for (int kk = 0; kk < 4; kk++) {
            uint32_t bv[8][2];
            #pragma unroll
            for (int dtp = 0; dtp < 4; dtp++)
                LDSM4T(bv[2*dtp][0], bv[2*dtp][1], bv[2*dtp+1][0], bv[2*dtp+1][1],
                       Vlb + (kk*16*PW + dtp*8)*4);
            #pragma unroll
            for (int mt = 0; mt < 2; mt++) {
                uint32_t af[4];
                af[0] = f2h2(S[mt][2*kk][0],   S[mt][2*kk][1]);
                af[1] = f2h2(S[mt][2*kk][2],   S[mt][2*kk][3]);
                af[2] = f2h2(S[mt][2*kk+1][0], S[mt][2*kk+1][1]);
                af[3] = f2h2(S[mt][2*kk+1][2], S[mt][2*kk+1][3]);
                #pragma unroll
                for (int dt = 0; dt < 8; dt++)
                    mma_f16(O[mt][dt], af, bv[dt]);
            }
        }
    }

    // write normalized output as fp16 (B,S,D)
    int gid = lane >> 2, q4 = lane & 3;
    #pragma unroll
    for (int mt = 0; mt < 2; mt++) {
        float inv_a = 1.f / l_a[mt];
        float inv_b = 1.f / l_b[mt];
        int rr = w*32 + mt*16 + gid;
        size_t base_a = ((size_t)b*SEQ + q0 + rr)*DIM + h*HD;
        size_t base_b = ((size_t)b*SEQ + q0 + rr + 8)*DIM + h*HD;
        #pragma unroll
        for (int dt = 0; dt < 8; dt++) {
            int col = dt*8 + 2*q4;
            *(uint32_t*)&g_attn[base_a + col] =
                f2h2(O[mt][dt][0]*inv_a, O[mt][dt][1]*inv_a);
            *(uint32_t*)&g_attn[base_b + col] =
                f2h2(O[mt][dt][2]*inv_b, O[mt][dt][3]*inv_b);
        }
    }
}

// ---------------------------------------------------------------------------
extern "C" void kernel_launch(void* const* d_in, const int* in_sizes, int n_in,
                              void* d_out, int out_size)
{
    const float* x      = (const float*)d_in[0];
    const float* w_qkv  = (const float*)d_in[1];
    const float* b_qkv  = (const float*)d_in[2];
    const float* w_out  = (const float*)d_in[3];
    const float* b_out  = (const float*)d_in[4];
    float* out = (float*)d_out;

    __half* xh_p;    cudaGetSymbolAddress((void**)&xh_p,    g_xh);
    __half* wqkvT_p; cudaGetSymbolAddress((void**)&wqkvT_p, g_wqkvT);
    __half* woutT_p; cudaGetSymbolAddress((void**)&woutT_p, g_woutT);

    // 0) prep: x -> fp16, weight transpose + fp16 convert
    xcvt<<<MTOK*DIM/4/256, 256>>>(x, xh_p);
    wtrans<<<dim3(3*DIM/32, DIM/32), dim3(32,8)>>>(w_qkv, wqkvT_p, DIM, 3*DIM);
    wtrans<<<dim3(DIM/32,   DIM/32), dim3(32,8)>>>(w_out, woutT_p, DIM, DIM);

    // 1) QKV projection + scatter (BK=64, 3-stage cp.async)
    cudaFuncSetAttribute(gemm_qkv,
        cudaFuncAttributeMaxDynamicSharedMemorySize, GEMM_SMEM);
    dim3 g1(3*DIM/128, MTOK/128);
    gemm_qkv<<<g1, 256, GEMM_SMEM>>>(b_qkv);

    // 2) fused attention (3-stage cp.async)
    size_t asmem = (size_t)ATT_SMEM_WORDS * sizeof(uint32_t);  // 73728 B
    cudaFuncSetAttribute(attn_kernel,
        cudaFuncAttributeMaxDynamicSharedMemorySize, (int)asmem);
    dim3 g2(SEQ/QT, NH, BATCH);
    attn_kernel<<<g2, 128, asmem>>>();

    // 3) output projection (BK=64, 3-stage cp.async)
    cudaFuncSetAttribute(gemm_out,
        cudaFuncAttributeMaxDynamicSharedMemorySize, GEMM_SMEM);
    dim3 g3(DIM/128, MTOK/128);
    gemm_out<<<g3, 256, GEMM_SMEM>>>(b_out, out);
}

// round 14
// speedup vs baseline: 1.0575x; 1.0575x over previous
#include <cuda_runtime.h>
#include <cuda_fp16.h>
#include <math.h>
#include <stdint.h>

#define BATCH 4
#define SEQ   2048
#define DIM   1024
#define NH    16
#define HD    64
#define MTOK  (BATCH*SEQ)        // 8192
#define SCALE_LOG2E 0.1803368801111204f   // (1/sqrt(64)) * log2(e)

// Scratch (allocation-free: __device__ globals), all fp16
__device__ __half g_xh[MTOK*DIM];          // fp16 copy of x
__device__ __half g_wqkvT[3*DIM*DIM];      // [3072][1024] = w_qkv^T
__device__ __half g_woutT[DIM*DIM];        // [1024][1024] = w_out^T
__device__ __half g_q[BATCH*NH*SEQ*HD];    // (B,H,S,Hd), pre-scaled by log2e/8
__device__ __half g_k[BATCH*NH*SEQ*HD];
__device__ __half g_v[BATCH*NH*SEQ*HD];
__device__ __half g_attn[MTOK*DIM];        // (B*S, D)

// ---------------------------------------------------------------------------
// helpers
// ---------------------------------------------------------------------------
__device__ __forceinline__ uint32_t f2h2(float lo, float hi) {
    __half2 h = __floats2half2_rn(lo, hi);
    return *reinterpret_cast<uint32_t*>(&h);
}

__device__ __forceinline__ float ex2f(float x) {
    float r;
    asm("ex2.approx.f32 %0, %1;" : "=f"(r) : "f"(x));
    return r;
}

__device__ __forceinline__ uint32_t smem_u32(const void* p) {
    uint32_t a;
    asm("{ .reg .u64 t; cvta.to.shared.u64 t, %1; cvt.u32.u64 %0, t; }"
        : "=r"(a) : "l"(p));
    return a;
}

__device__ __forceinline__ void mma_f16(float c[4],
                                        const uint32_t a[4],
                                        const uint32_t b[2]) {
    asm volatile(
        "mma.sync.aligned.m16n8k16.row.col.f32.f16.f16.f32 "
        "{%0,%1,%2,%3},{%4,%5,%6,%7},{%8,%9},{%0,%1,%2,%3};"
        : "+f"(c[0]), "+f"(c[1]), "+f"(c[2]), "+f"(c[3])
        : "r"(a[0]), "r"(a[1]), "r"(a[2]), "r"(a[3]),
          "r"(b[0]), "r"(b[1]));
}

#define LDSM4(r0, r1, r2, r3, addr) \
    asm volatile("ldmatrix.sync.aligned.m8n8.x4.shared.b16 {%0,%1,%2,%3},[%4];" \
        : "=r"(r0), "=r"(r1), "=r"(r2), "=r"(r3) : "r"(addr))

#define LDSM4T(r0, r1, r2, r3, addr) \
    asm volatile("ldmatrix.sync.aligned.m8n8.x4.trans.shared.b16 {%0,%1,%2,%3},[%4];" \
        : "=r"(r0), "=r"(r1), "=r"(r2), "=r"(r3) : "r"(addr))

#define CPA16(saddr, gptr) \
    asm volatile("cp.async.cg.shared.global [%0], [%1], 16;" \
        :: "r"(saddr), "l"(gptr) : "memory")
#define CP_COMMIT() asm volatile("cp.async.commit_group;" ::: "memory")
#define CP_WAIT3()  asm volatile("cp.async.wait_group 3;" ::: "memory")
#define CP_WAIT2()  asm volatile("cp.async.wait_group 2;" ::: "memory")
#define CP_WAIT1()  asm volatile("cp.async.wait_group 1;" ::: "memory")
#define CP_WAIT0()  asm volatile("cp.async.wait_group 0;" ::: "memory")

// ---------------------------------------------------------------------------
// prep kernels
// ---------------------------------------------------------------------------
__global__ void xcvt(const float* __restrict__ x, __half* __restrict__ dst)
{
    int i = blockIdx.x * blockDim.x + threadIdx.x;   // over float4s
    float4 v = ((const float4*)x)[i];
    uint2 u;
    u.x = f2h2(v.x, v.y);
    u.y = f2h2(v.z, v.w);
    ((uint2*)dst)[i] = u;
}

__global__ void wtrans(const float* __restrict__ src, __half* __restrict__ dst,
                       int K, int N)
{
    __shared__ float sm[32][33];
    int tx = threadIdx.x, ty = threadIdx.y;
    int n0 = blockIdx.x * 32, k0 = blockIdx.y * 32;
    #pragma unroll
    for (int j = 0; j < 32; j += 8)
        sm[ty + j][tx] = src[(size_t)(k0 + ty + j)*N + n0 + tx];
    __syncthreads();
    #pragma unroll
    for (int j = 0; j < 32; j += 8)
        dst[(size_t)(n0 + ty + j)*K + k0 + tx] = __float2half(sm[tx][ty + j]);
}

// ---------------------------------------------------------------------------
// fp16 MMA GEMM, 5-stage cp.async ring (BK=32), one __syncthreads per k-step,
// prefetch issued immediately after the barrier (before compute).
// 128x128 block, 256 threads = 8 warps (2x4), warp tile 64x32.
// SMEM [row][k-word], pitch 20 (conflict-free LDSM). Dynamic SMEM: 100 KB.
// ---------------------------------------------------------------------------
#define KPW 20
#define NKB (DIM/32)            // 32
#define GSTG 5
#define STGB (128*KPW*4)        // 10240 B per stage per operand
#define GEMM_SMEM (2*GSTG*STGB) // 102400

__device__ __forceinline__ void comp16(uint32_t Aln, uint32_t Bln,
                                       float acc[4][4][4]) {
    #pragma unroll
    for (int st = 0; st < 2; st++) {
        uint32_t af[4][4], bf[4][2];
        #pragma unroll
        for (int mt = 0; mt < 4; mt++)
            LDSM4(af[mt][0], af[mt][1], af[mt][2], af[mt][3],
                  Aln + (mt*16*KPW + st*8)*4);
        #pragma unroll
        for (int ntp = 0; ntp < 2; ntp++)
            LDSM4(bf[2*ntp][0], bf[2*ntp][1], bf[2*ntp+1][0], bf[2*ntp+1][1],
                  Bln + (ntp*16*KPW + st*8)*4);
        #pragma unroll
        for (int mt = 0; mt < 4; mt++)
            #pragma unroll
            for (int nt = 0; nt < 4; nt++)
                mma_f16(acc[mt][nt], af[mt], bf[nt]);
    }
}

// 5-stage mainloop: prefetch-early ordering.
#define GEMM_PIPE(aRow, bRow)                                                  \
    extern __shared__ uint32_t dsm[];                                          \
    uint32_t aBase = smem_u32(dsm);                                            \
    uint32_t bBase = aBase + GSTG*STGB;                                        \
    uint32_t sA0 = aBase + (r*KPW + 8*h)*4;                                    \
    uint32_t sB0 = bBase + (r*KPW + 8*h)*4;                                    \
    uint32_t Aln0 = aBase + (((wr*64 + (mid&1)*8 + l7)*KPW) + (mid>>1)*4)*4;   \
    uint32_t Bln0 = bBase + (((wc*32 + (mid>>1)*8 + l7)*KPW) + (mid&1)*4)*4;   \
    _Pragma("unroll")                                                          \
    for (int s = 0; s < GSTG-1; s++) {                                         \
        const __half* ga = (aRow) + s*32;                                      \
        const __half* gb = (bRow) + s*32;                                      \
        CPA16(sA0 + s*STGB, ga);  CPA16(sA0 + s*STGB + 16, ga + 8);            \
        CPA16(sB0 + s*STGB, gb);  CPA16(sB0 + s*STGB + 16, gb + 8);            \
        CP_COMMIT();                                                           \
    }                                                                          \
    for (int kb = 0; kb < NKB; kb++) {                                         \
        int rem = NKB - 1 - kb;                                                \
        if (rem >= 3)      CP_WAIT3();                                         \
        else if (rem == 2) CP_WAIT2();                                         \
        else if (rem == 1) CP_WAIT1();                                         \
        else               CP_WAIT0();                                         \
        __syncthreads();                                                       \
        int nk = kb + GSTG - 1;                                                \
        if (nk < NKB) {                                                        \
            int sl = nk % GSTG;                                                \
            const __half* ga = (aRow) + nk*32;                                 \
            const __half* gb = (bRow) + nk*32;                                 \
            CPA16(sA0 + sl*STGB, ga);  CPA16(sA0 + sl*STGB + 16, ga + 8);      \
            CPA16(sB0 + sl*STGB, gb);  CPA16(sB0 + sl*STGB + 16, gb + 8);      \
            CP_COMMIT();                                                       \
        }                                                                      \
        int cl = kb % GSTG;                                                    \
        comp16(Aln0 + cl*STGB, Bln0 + cl*STGB, acc);                           \
    }

// ---- qkv GEMM: xh(fp16) @ wqkvT(fp16) + bias -> scatter g_q/g_k/g_v (fp16)
__global__ void __launch_bounds__(256) gemm_qkv(const float* __restrict__ bias)
{
    int tid = threadIdx.x, lane = tid & 31, wid = tid >> 5;
    int wr = wid >> 2, wc = wid & 3, gid = lane >> 2, q4 = lane & 3;
    int row0 = blockIdx.y * 128, col0 = blockIdx.x * 128;
    int r = tid >> 1, h = tid & 1;
    int mid = lane >> 3, l7 = lane & 7;

    float acc[4][4][4];
    #pragma unroll
    for (int mt = 0; mt < 4; mt++)
        #pragma unroll
        for (int nt = 0; nt < 4; nt++)
            #pragma unroll
            for (int e = 0; e < 4; e++) acc[mt][nt][e] = 0.f;

    const __half* aRow = g_xh    + (size_t)(row0 + r)*DIM + 16*h;
    const __half* bRow = g_wqkvT + (size_t)(col0 + r)*DIM + 16*h;

    GEMM_PIPE(aRow, bRow)

    // epilogue: +bias, scatter as half2
    #pragma unroll
    for (int mt = 0; mt < 4; mt++) {
        #pragma unroll
        for (int nt = 0; nt < 4; nt++) {
            int col = col0 + wc*32 + nt*8 + 2*q4;
            float2 bs = *(const float2*)&bias[col];
            int three = col >> 10;
            int rem   = col & 1023;
            int hh    = rem >> 6;
            int hd    = rem & 63;
            float sc = (three == 0) ? SCALE_LOG2E : 1.f;
            __half* dstb = (three == 0) ? g_q : (three == 1) ? g_k : g_v;
            #pragma unroll
            for (int half_i = 0; half_i < 2; half_i++) {
                int row = row0 + wr*64 + mt*16 + gid + half_i*8;
                int b  = row >> 11;
                int s  = row & 2047;
                float v0 = (acc[mt][nt][2*half_i]   + bs.x) * sc;
                float v1 = (acc[mt][nt][2*half_i+1] + bs.y) * sc;
                size_t dst = ((size_t)(b*NH + hh)*SEQ + s)*HD + hd;
                *(uint32_t*)&dstb[dst] = f2h2(v0, v1);
            }
        }
    }
}

// ---- out GEMM: g_attn(fp16) @ woutT(fp16) + bias -> d_out (fp32)
__global__ void __launch_bounds__(256) gemm_out(
    const float* __restrict__ bias, float* __restrict__ C)
{
    int tid = threadIdx.x, lane = tid & 31, wid = tid >> 5;
    int wr = wid >> 2, wc = wid & 3, gid = lane >> 2, q4 = lane & 3;
    int row0 = blockIdx.y * 128, col0 = blockIdx.x * 128;
    int r = tid >> 1, h = tid & 1;
    int mid = lane >> 3, l7 = lane & 7;

    float acc[4][4][4];
    #pragma unroll
    for (int mt = 0; mt < 4; mt++)
        #pragma unroll
        for (int nt = 0; nt < 4; nt++)
            #pragma unroll
            for (int e = 0; e < 4; e++) acc[mt][nt][e] = 0.f;

    const __half* aRow = g_attn  + (size_t)(row0 + r)*DIM + 16*h;
    const __half* bRow = g_woutT + (size_t)(col0 + r)*DIM + 16*h;

    GEMM_PIPE(aRow, bRow)

    #pragma unroll
    for (int mt = 0; mt < 4; mt++) {
        #pragma unroll
        for (int nt = 0; nt < 4; nt++) {
            int col = col0 + wc*32 + nt*8 + 2*q4;
            float2 bs = *(const float2*)&bias[col];
            #pragma unroll
            for (int half_i = 0; half_i < 2; half_i++) {
                int row = row0 + wr*64 + mt*16 + gid + half_i*8;
                float2 v;
                v.x = acc[mt][nt][2*half_i]   + bs.x;
                v.y = acc[mt][nt][2*half_i+1] + bs.y;
                *(float2*)&C[(size_t)row*DIM + col] = v;
            }
        }
    }
}

// ---------------------------------------------------------------------------
// Fused flash attention (exactly round-12 measured-best): fp16 m16n8k16,
// register-resident P, ldmatrix loads, 3-stage cp.async ring for K/V tiles.
// QT=128, 128 threads = 4 warps, warp owns 32 q-rows (2 m16 tiles).
// ---------------------------------------------------------------------------
#define QT 128
#define KT 64
#define PW 36
#define ASTG 3
#define KVSTGB (KT*PW*4)
#define ATT_SMEM_WORDS ((QT + 2*ASTG*KT) * PW)   // 18432 words = 73728 B

__global__ void __launch_bounds__(128, 3) attn_kernel()
{
    extern __shared__ uint32_t smu[];
    uint32_t (*Qs)[PW] = (uint32_t (*)[PW])smu;      // [128 q][32 dw]
    uint32_t kBase = smem_u32(smu + QT*PW);          // K: 3 stages
    uint32_t vBase = kBase + ASTG*KVSTGB;            // V: 3 stages

    int tid  = threadIdx.x;
    int lane = tid & 31;
    int w    = tid >> 5;
    int mid  = lane >> 3, l7 = lane & 7;

    int b  = blockIdx.z;
    int h  = blockIdx.y;
    int q0 = blockIdx.x * QT;

    const __half* qptr = g_q + ((size_t)(b*NH + h)*SEQ)*HD;
    const __half* kptr = g_k + ((size_t)(b*NH + h)*SEQ)*HD;
    const __half* vptr = g_v + ((size_t)(b*NH + h)*SEQ)*HD;

    int sr = tid >> 3;          // 0..15
    int scu = tid & 7;          // 0..7
    uint32_t sK0 = kBase + (sr*PW + scu*4)*4;
    uint32_t sV0 = vBase + (sr*PW + scu*4)*4;

    uint32_t Qln = smem_u32(Qs) + (((w*32 + (mid&1)*8 + l7)*PW) + (mid>>1)*4)*4;
    uint32_t Kln = kBase + ((((mid>>1)*8 + l7)*PW) + (mid&1)*4)*4;
    uint32_t Vln = vBase + ((((mid&1)*8 + l7)*PW) + (mid>>1)*4)*4;

    // load Q tile (128x64 halves) via uint4 copies
    #pragma unroll
    for (int it = 0; it < 8; it++) {
        int u  = tid + it*128;
        int r  = u >> 3;
        int cu = u & 7;
        uint4 v = *(const uint4*)&qptr[(size_t)(q0 + r)*HD + cu*8];
        *(uint4*)&Qs[r][cu*4] = v;
    }

    // prefetch K/V tiles 0,1 into stages 0,1
    #pragma unroll
    for (int s = 0; s < ASTG-1; s++) {
        #pragma unroll
        for (int it = 0; it < 4; it++) {
            int r = s*KT + sr + it*16;
            CPA16(sK0 + s*KVSTGB + it*16*PW*4, &kptr[(size_t)r*HD + scu*8]);
            CPA16(sV0 + s*KVSTGB + it*16*PW*4, &vptr[(size_t)r*HD + scu*8]);
        }
        CP_COMMIT();
    }

    float m_a[2], m_b[2], l_a[2], l_b[2];
    float O[2][8][4];
    #pragma unroll
    for (int mt = 0; mt < 2; mt++) {
        m_a[mt] = -INFINITY; m_b[mt] = -INFINITY;
        l_a[mt] = 0.f; l_b[mt] = 0.f;
        #pragma unroll
        for (int dt = 0; dt < 8; dt++)
            #pragma unroll
            for (int e = 0; e < 4; e++) O[mt][dt][e] = 0.f;
    }

    const int NTI = SEQ/KT;   // 32
    for (int ti = 0; ti < NTI; ti++) {
        if (ti + 1 < NTI) CP_WAIT1();
        else              CP_WAIT0();
        __syncthreads();

        int sl = ti % ASTG;
        uint32_t Klb = Kln + sl*KVSTGB;
        uint32_t Vlb = Vln + sl*KVSTGB;

        // S = Q @ K^T
        float S[2][8][4];
        #pragma unroll
        for (int mt = 0; mt < 2; mt++)
            #pragma unroll
            for (int nt = 0; nt < 8; nt++)
                #pragma unroll
                for (int e = 0; e < 4; e++) S[mt][nt][e] = 0.f;

        #pragma unroll
        for (int kk = 0; kk < 4; kk++) {
            uint32_t bf[8][2];
            #pragma unroll
            for (int ntp = 0; ntp < 4; ntp++)
                LDSM4(bf[2*ntp][0], bf[2*ntp][1], bf[2*ntp+1][0], bf[2*ntp+1][1],
                      Klb + (ntp*16*PW + kk*8)*4);
            #pragma unroll
            for (int mt = 0; mt < 2; mt++) {
                uint32_t qf[4];
                LDSM4(qf[0], qf[1], qf[2], qf[3],
                      Qln + (mt*16*PW + kk*8)*4);
                #pragma unroll
                for (int nt = 0; nt < 8; nt++)
                    mma_f16(S[mt][nt], qf, bf[nt]);
            }
        }

        // prefetch tile ti+2
        int nt2 = ti + ASTG - 1;
        if (nt2 < NTI) {
            int ps = nt2 % ASTG;
            #pragma unroll
            for (int it = 0; it < 4; it++) {
                int r = nt2*KT + sr + it*16;
                CPA16(sK0 + ps*KVSTGB + it*16*PW*4, &kptr[(size_t)r*HD + scu*8]);
                CPA16(sV0 + ps*KVSTGB + it*16*PW*4, &vptr[(size_t)r*HD + scu*8]);
            }
            CP_COMMIT();
        }

        // online softmax (exp2 domain)
        #pragma unroll
        for (int mt = 0; mt < 2; mt++) {
            float ma = S[mt][0][0], mb = S[mt][0][2];
            #pragma unroll
            for (int nt = 0; nt < 8; nt++) {
                ma = fmaxf(ma, fmaxf(S[mt][nt][0], S[mt][nt][1]));
                mb = fmaxf(mb, fmaxf(S[mt][nt][2], S[mt][nt][3]));
            }
            #pragma unroll
            for (int off = 1; off <= 2; off <<= 1) {
                ma = fmaxf(ma, __shfl_xor_sync(0xffffffffu, ma, off));
                mb = fmaxf(mb, __shfl_xor_sync(0xffffffffu, mb, off));
            }
            float mna = fmaxf(m_a[mt], ma);
            float mnb = fmaxf(m_b[mt], mb);
            float alpha_a = ex2f(m_a[mt] - mna);
            float alpha_b = ex2f(m_b[mt] - mnb);
            float sa = 0.f, sb = 0.f;
            #pragma unroll
            for (int nt = 0; nt < 8; nt++) {
                S[mt][nt][0] = ex2f(S[mt][nt][0] - mna);
                S[mt][nt][1] = ex2f(S[mt][nt][1] - mna);
                S[mt][nt][2] = ex2f(S[mt][nt][2] - mnb);
                S[mt][nt][3] = ex2f(S[mt][nt][3] - mnb);
                sa += S[mt][nt][0] + S[mt][nt][1];
                sb += S[mt][nt][2] + S[mt][nt][3];
            }
            #pragma unroll
            for (int off = 1; off <= 2; off <<= 1) {
                sa += __shfl_xor_sync(0xffffffffu, sa, off);
                sb += __shfl_xor_sync(0xffffffffu, sb, off);
            }
            l_a[mt] = l_a[mt] * alpha_a + sa;
            l_b[mt] = l_b[mt] * alpha_b + sb;
            m_a[mt] = mna; m_b[mt] = mnb;
            #pragma unroll
            for (int dt = 0; dt < 8; dt++) {
                O[mt][dt][0] *= alpha_a; O[mt][dt][1] *= alpha_a;
                O[mt][dt][2] *= alpha_b; O[mt][dt][3] *= alpha_b;
            }
        }

        // O += P @ V (register P, ldmatrix.trans V)
        #pragma unroll
        for (int kk = 0; kk < 4; kk++) {
            uint32_t bv[8][2];
            #pragma unroll
            for (int dtp = 0; dtp < 4; dtp++)
                LDSM4T(bv[2*dtp][0], bv[2*dtp][1], bv[2*dtp+1][0], bv[2*dtp+1][1],
                       Vlb + (kk*16*PW + dtp*8)*4);
            #pragma unroll
            for (int mt = 0; mt < 2; mt++) {
                uint32_t af[4];
                af[0] = f2h2(S[mt][2*kk][0],   S[mt][2*kk][1]);
                af[1] = f2h2(S[mt][2*kk][2],   S[mt][2*kk][3]);
                af[2] = f2h2(S[mt][2*kk+1][0], S[mt][2*kk+1][1]);
                af[3] = f2h2(S[mt][2*kk+1][2], S[mt][2*kk+1][3]);
                #pragma unroll
                for (int dt = 0; dt < 8; dt++)
                    mma_f16(O[mt][dt], af, bv[dt]);
            }
        }
    }

    // write normalized output as fp16 (B,S,D)
    int gid = lane >> 2, q4 = lane & 3;
    #pragma unroll
    for (int mt = 0; mt < 2; mt++) {
        float inv_a = 1.f / l_a[mt];
        float inv_b = 1.f / l_b[mt];
        int rr = w*32 + mt*16 + gid;
        size_t base_a = ((size_t)b*SEQ + q0 + rr)*DIM + h*HD;
        size_t base_b = ((size_t)b*SEQ + q0 + rr + 8)*DIM + h*HD;
        #pragma unroll
        for (int dt = 0; dt < 8; dt++) {
            int col = dt*8 + 2*q4;
            *(uint32_t*)&g_attn[base_a + col] =
                f2h2(O[mt][dt][0]*inv_a, O[mt][dt][1]*inv_a);
            *(uint32_t*)&g_attn[base_b + col] =
                f2h2(O[mt][dt][2]*inv_b, O[mt][dt][3]*inv_b);
        }
    }
}

// ---------------------------------------------------------------------------
extern "C" void kernel_launch(void* const* d_in, const int* in_sizes, int n_in,
                              void* d_out, int out_size)
{
    const float* x      = (const float*)d_in[0];
    const float* w_qkv  = (const float*)d_in[1];
    const float* b_qkv  = (const float*)d_in[2];
    const float* w_out  = (const float*)d_in[3];
    const float* b_out  = (const float*)d_in[4];
    float* out = (float*)d_out;

    __half* xh_p;    cudaGetSymbolAddress((void**)&xh_p,    g_xh);
    __half* wqkvT_p; cudaGetSymbolAddress((void**)&wqkvT_p, g_wqkvT);
    __half* woutT_p; cudaGetSymbolAddress((void**)&woutT_p, g_woutT);

    // 0) prep: x -> fp16, weight transpose + fp16 convert
    xcvt<<<MTOK*DIM/4/256, 256>>>(x, xh_p);
    wtrans<<<dim3(3*DIM/32, DIM/32), dim3(32,8)>>>(w_qkv, wqkvT_p, DIM, 3*DIM);
    wtrans<<<dim3(DIM/32,   DIM/32), dim3(32,8)>>>(w_out, woutT_p, DIM, DIM);

    // 1) QKV projection + scatter (5-stage cp.async, prefetch-early)
    cudaFuncSetAttribute(gemm_qkv,
        cudaFuncAttributeMaxDynamicSharedMemorySize, GEMM_SMEM);
    dim3 g1(3*DIM/128, MTOK/128);
    gemm_qkv<<<g1, 256, GEMM_SMEM>>>(b_qkv);

    // 2) fused attention (round-12 exact)
    size_t asmem = (size_t)ATT_SMEM_WORDS * sizeof(uint32_t);  // 73728 B
    cudaFuncSetAttribute(attn_kernel,
        cudaFuncAttributeMaxDynamicSharedMemorySize, (int)asmem);
    dim3 g2(SEQ/QT, NH, BATCH);
    attn_kernel<<<g2, 128, asmem>>>();

    // 3) output projection (5-stage cp.async, prefetch-early)
    cudaFuncSetAttribute(gemm_out,
        cudaFuncAttributeMaxDynamicSharedMemorySize, GEMM_SMEM);
    dim3 g3(DIM/128, MTOK/128);
    gemm_out<<<g3, 256, GEMM_SMEM>>>(b_out, out);
}

// round 15
// speedup vs baseline: 1.1690x; 1.1055x over previous
#include <cuda_runtime.h>
#include <cuda_fp16.h>
#include <math.h>
#include <stdint.h>

#define BATCH 4
#define SEQ   2048
#define DIM   1024
#define NH    16
#define HD    64
#define MTOK  (BATCH*SEQ)        // 8192
#define SCALE_LOG2E 0.1803368801111204f   // (1/sqrt(64)) * log2(e)

// Scratch (allocation-free: __device__ globals), all fp16
__device__ __half g_xh[MTOK*DIM];          // fp16 copy of x
__device__ __half g_wqkvT[3*DIM*DIM];      // [3072][1024] = w_qkv^T
__device__ __half g_woutT[DIM*DIM];        // [1024][1024] = w_out^T
__device__ __half g_q[BATCH*NH*SEQ*HD];    // (B,H,S,Hd), pre-scaled by log2e/8
__device__ __half g_k[BATCH*NH*SEQ*HD];
__device__ __half g_v[BATCH*NH*SEQ*HD];
__device__ __half g_attn[MTOK*DIM];        // (B*S, D)

// ---------------------------------------------------------------------------
// helpers
// ---------------------------------------------------------------------------
__device__ __forceinline__ uint32_t f2h2(float lo, float hi) {
    __half2 h = __floats2half2_rn(lo, hi);
    return *reinterpret_cast<uint32_t*>(&h);
}

__device__ __forceinline__ float ex2f(float x) {
    float r;
    asm("ex2.approx.f32 %0, %1;" : "=f"(r) : "f"(x));
    return r;
}

__device__ __forceinline__ uint32_t ex2h2(uint32_t x) {
    uint32_t r;
    asm("ex2.approx.f16x2 %0, %1;" : "=r"(r) : "r"(x));
    return r;
}

__device__ __forceinline__ uint32_t smem_u32(const void* p) {
    uint32_t a;
    asm("{ .reg .u64 t; cvta.to.shared.u64 t, %1; cvt.u32.u64 %0, t; }"
        : "=r"(a) : "l"(p));
    return a;
}

__device__ __forceinline__ void mma_f16(float c[4],
                                        const uint32_t a[4],
                                        const uint32_t b[2]) {
    asm volatile(
        "mma.sync.aligned.m16n8k16.row.col.f32.f16.f16.f32 "
        "{%0,%1,%2,%3},{%4,%5,%6,%7},{%8,%9},{%0,%1,%2,%3};"
        : "+f"(c[0]), "+f"(c[1]), "+f"(c[2]), "+f"(c[3])
        : "r"(a[0]), "r"(a[1]), "r"(a[2]), "r"(a[3]),
          "r"(b[0]), "r"(b[1]));
}

#define LDSM4(r0, r1, r2, r3, addr) \
    asm volatile("ldmatrix.sync.aligned.m8n8.x4.shared.b16 {%0,%1,%2,%3},[%4];" \
        : "=r"(r0), "=r"(r1), "=r"(r2), "=r"(r3) : "r"(addr))

#define LDSM4T(r0, r1, r2, r3, addr) \
    asm volatile("ldmatrix.sync.aligned.m8n8.x4.trans.shared.b16 {%0,%1,%2,%3},[%4];" \
        : "=r"(r0), "=r"(r1), "=r"(r2), "=r"(r3) : "r"(addr))

#define CPA16(saddr, gptr) \
    asm volatile("cp.async.cg.shared.global [%0], [%1], 16;" \
        :: "r"(saddr), "l"(gptr) : "memory")
#define CP_COMMIT() asm volatile("cp.async.commit_group;" ::: "memory")
#define CP_WAIT2()  asm volatile("cp.async.wait_group 2;" ::: "memory")
#define CP_WAIT1()  asm volatile("cp.async.wait_group 1;" ::: "memory")
#define CP_WAIT0()  asm volatile("cp.async.wait_group 0;" ::: "memory")

// ---------------------------------------------------------------------------
// prep kernels
// ---------------------------------------------------------------------------
__global__ void xcvt(const float* __restrict__ x, __half* __restrict__ dst)
{
    int i = blockIdx.x * blockDim.x + threadIdx.x;   // over float4s
    float4 v = ((const float4*)x)[i];
    uint2 u;
    u.x = f2h2(v.x, v.y);
    u.y = f2h2(v.z, v.w);
    ((uint2*)dst)[i] = u;
}

__global__ void wtrans(const float* __restrict__ src, __half* __restrict__ dst,
                       int K, int N)
{
    __shared__ float sm[32][33];
    int tx = threadIdx.x, ty = threadIdx.y;
    int n0 = blockIdx.x * 32, k0 = blockIdx.y * 32;
    #pragma unroll
    for (int j = 0; j < 32; j += 8)
        sm[ty + j][tx] = src[(size_t)(k0 + ty + j)*N + n0 + tx];
    __syncthreads();
    #pragma unroll
    for (int j = 0; j < 32; j += 8)
        dst[(size_t)(n0 + ty + j)*K + k0 + tx] = __float2half(sm[tx][ty + j]);
}

// ---------------------------------------------------------------------------
// fp16 MMA GEMM, 4-stage cp.async ring (exact round-12 measured-best).
// 128x128 block, BK=32, 256 threads = 8 warps (2x4), warp tile 64x32.
// SMEM [row][k-word], pitch 20 (conflict-free LDSM). Dynamic SMEM: 80 KB.
// ---------------------------------------------------------------------------
#define KPW 20
#define NKB (DIM/32)            // 32
#define GSTG 4
#define STGB (128*KPW*4)        // bytes per stage per operand
#define GEMM_SMEM (2*GSTG*STGB) // 81920

__device__ __forceinline__ void comp16(uint32_t Aln, uint32_t Bln,
                                       float acc[4][4][4]) {
    #pragma unroll
    for (int st = 0; st < 2; st++) {
        uint32_t af[4][4], bf[4][2];
        #pragma unroll
        for (int mt = 0; mt < 4; mt++)
            LDSM4(af[mt][0], af[mt][1], af[mt][2], af[mt][3],
                  Aln + (mt*16*KPW + st*8)*4);
        #pragma unroll
        for (int ntp = 0; ntp < 2; ntp++)
            LDSM4(bf[2*ntp][0], bf[2*ntp][1], bf[2*ntp+1][0], bf[2*ntp+1][1],
                  Bln + (ntp*16*KPW + st*8)*4);
        #pragma unroll
        for (int mt = 0; mt < 4; mt++)
            #pragma unroll
            for (int nt = 0; nt < 4; nt++)
                mma_f16(acc[mt][nt], af[mt], bf[nt]);
    }
}

#define GEMM_PIPE(aRow, bRow)                                                  \
    extern __shared__ uint32_t dsm[];                                          \
    uint32_t aBase = smem_u32(dsm);                                            \
    uint32_t bBase = aBase + GSTG*STGB;                                        \
    uint32_t sA0 = aBase + (r*KPW + 8*h)*4;                                    \
    uint32_t sB0 = bBase + (r*KPW + 8*h)*4;                                    \
    uint32_t Aln0 = aBase + (((wr*64 + (mid&1)*8 + l7)*KPW) + (mid>>1)*4)*4;   \
    uint32_t Bln0 = bBase + (((wc*32 + (mid>>1)*8 + l7)*KPW) + (mid&1)*4)*4;   \
    _Pragma("unroll")                                                          \
    for (int s = 0; s < GSTG-1; s++) {                                         \
        const __half* ga = (aRow) + s*32;                                      \
        const __half* gb = (bRow) + s*32;                                      \
        CPA16(sA0 + s*STGB, ga);  CPA16(sA0 + s*STGB + 16, ga + 8);            \
        CPA16(sB0 + s*STGB, gb);  CPA16(sB0 + s*STGB + 16, gb + 8);            \
        CP_COMMIT();                                                           \
    }                                                                          \
    for (int kb = 0; kb < NKB; kb++) {                                         \
        if (kb + 2 < NKB)      CP_WAIT2();                                     \
        else if (kb + 1 < NKB) CP_WAIT1();                                     \
        else                   CP_WAIT0();                                     \
        __syncthreads();                                                       \
        comp16(Aln0 + (kb & 3)*STGB, Bln0 + (kb & 3)*STGB, acc);               \
        int nk = kb + GSTG - 1;                                                \
        if (nk < NKB) {                                                        \
            int sl = nk & 3;                                                   \
            const __half* ga = (aRow) + nk*32;                                 \
            const __half* gb = (bRow) + nk*32;                                 \
            CPA16(sA0 + sl*STGB, ga);  CPA16(sA0 + sl*STGB + 16, ga + 8);      \
            CPA16(sB0 + sl*STGB, gb);  CPA16(sB0 + sl*STGB + 16, gb + 8);      \
            CP_COMMIT();                                                       \
        }                                                                      \
    }

// ---- qkv GEMM: xh(fp16) @ wqkvT(fp16) + bias -> scatter g_q/g_k/g_v (fp16)
__global__ void __launch_bounds__(256) gemm_qkv(const float* __restrict__ bias)
{
    int tid = threadIdx.x, lane = tid & 31, wid = tid >> 5;
    int wr = wid >> 2, wc = wid & 3, gid = lane >> 2, q4 = lane & 3;
    int row0 = blockIdx.y * 128, col0 = blockIdx.x * 128;
    int r = tid >> 1, h = tid & 1;
    int mid = lane >> 3, l7 = lane & 7;

    float acc[4][4][4];
    #pragma unroll
    for (int mt = 0; mt < 4; mt++)
        #pragma unroll
        for (int nt = 0; nt < 4; nt++)
            #pragma unroll
            for (int e = 0; e < 4; e++) acc[mt][nt][e] = 0.f;

    const __half* aRow = g_xh    + (size_t)(row0 + r)*DIM + 16*h;
    const __half* bRow = g_wqkvT + (size_t)(col0 + r)*DIM + 16*h;

    GEMM_PIPE(aRow, bRow)

    // epilogue: +bias, scatter as half2
    #pragma unroll
    for (int mt = 0; mt < 4; mt++) {
        #pragma unroll
        for (int nt = 0; nt < 4; nt++) {
            int col = col0 + wc*32 + nt*8 + 2*q4;
            float2 bs = *(const float2*)&bias[col];
            int three = col >> 10;
            int rem   = col & 1023;
            int hh    = rem >> 6;
            int hd    = rem & 63;
            float sc = (three == 0) ? SCALE_LOG2E : 1.f;
            __half* dstb = (three == 0) ? g_q : (three == 1) ? g_k : g_v;
            #pragma unroll
            for (int half_i = 0; half_i < 2; half_i++) {
                int row = row0 + wr*64 + mt*16 + gid + half_i*8;
                int b  = row >> 11;
                int s  = row & 2047;
                float v0 = (acc[mt][nt][2*half_i]   + bs.x) * sc;
                float v1 = (acc[mt][nt][2*half_i+1] + bs.y) * sc;
                size_t dst = ((size_t)(b*NH + hh)*SEQ + s)*HD + hd;
                *(uint32_t*)&dstb[dst] = f2h2(v0, v1);
            }
        }
    }
}

// ---- out GEMM: g_attn(fp16) @ woutT(fp16) + bias -> d_out (fp32)
__global__ void __launch_bounds__(256) gemm_out(
    const float* __restrict__ bias, float* __restrict__ C)
{
    int tid = threadIdx.x, lane = tid & 31, wid = tid >> 5;
    int wr = wid >> 2, wc = wid & 3, gid = lane >> 2, q4 = lane & 3;
    int row0 = blockIdx.y * 128, col0 = blockIdx.x * 128;
    int r = tid >> 1, h = tid & 1;
    int mid = lane >> 3, l7 = lane & 7;

    float acc[4][4][4];
    #pragma unroll
    for (int mt = 0; mt < 4; mt++)
        #pragma unroll
        for (int nt = 0; nt < 4; nt++)
            #pragma unroll
            for (int e = 0; e < 4; e++) acc[mt][nt][e] = 0.f;

    const __half* aRow = g_attn  + (size_t)(row0 + r)*DIM + 16*h;
    const __half* bRow = g_woutT + (size_t)(col0 + r)*DIM + 16*h;

    GEMM_PIPE(aRow, bRow)

    #pragma unroll
    for (int mt = 0; mt < 4; mt++) {
        #pragma unroll
        for (int nt = 0; nt < 4; nt++) {
            int col = col0 + wc*32 + nt*8 + 2*q4;
            float2 bs = *(const float2*)&bias[col];
            #pragma unroll
            for (int half_i = 0; half_i < 2; half_i++) {
                int row = row0 + wr*64 + mt*16 + gid + half_i*8;
                float2 v;
                v.x = acc[mt][nt][2*half_i]   + bs.x;
                v.y = acc[mt][nt][2*half_i+1] + bs.y;
                *(float2*)&C[(size_t)row*DIM + col] = v;
            }
        }
    }
}

// ---------------------------------------------------------------------------
// Fused flash attention: fp16 m16n8k16, register-resident P, ldmatrix loads,
// 3-stage cp.async K/V ring. NEW vs round-12:
//  - softmax sum l computed by the tensor core (mma of P against all-ones B,
//    accumulated in Lacc with the same alpha rescaling as O) -> no per-tile
//    sum adds, no sum shuffles.
//  - P = ex2.approx.f16x2 on packed (S - m): output IS the PV a-fragment,
//    stored bit-cast back into the S registers (no extra registers).
// ---------------------------------------------------------------------------
#define QT 128
#define KT 64
#define PW 36
#define ASTG 3
#define KVSTGB (KT*PW*4)
#define ATT_SMEM_WORDS ((QT + 2*ASTG*KT) * PW)   // 18432 words = 73728 B
#define ONES_H2 0x3C003C00u

__global__ void __launch_bounds__(128, 3) attn_kernel()
{
    extern __shared__ uint32_t smu[];
    uint32_t (*Qs)[PW] = (uint32_t (*)[PW])smu;      // [128 q][32 dw]
    uint32_t kBase = smem_u32(smu + QT*PW);          // K: 3 stages
    uint32_t vBase = kBase + ASTG*KVSTGB;            // V: 3 stages

    int tid  = threadIdx.x;
    int lane = tid & 31;
    int w    = tid >> 5;
    int mid  = lane >> 3, l7 = lane & 7;

    int b  = blockIdx.z;
    int h  = blockIdx.y;
    int q0 = blockIdx.x * QT;

    const __half* qptr = g_q + ((size_t)(b*NH + h)*SEQ)*HD;
    const __half* kptr = g_k + ((size_t)(b*NH + h)*SEQ)*HD;
    const __half* vptr = g_v + ((size_t)(b*NH + h)*SEQ)*HD;

    int sr = tid >> 3;          // 0..15
    int scu = tid & 7;          // 0..7
    uint32_t sK0 = kBase + (sr*PW + scu*4)*4;
    uint32_t sV0 = vBase + (sr*PW + scu*4)*4;

    uint32_t Qln = smem_u32(Qs) + (((w*32 + (mid&1)*8 + l7)*PW) + (mid>>1)*4)*4;
    uint32_t Kln = kBase + ((((mid>>1)*8 + l7)*PW) + (mid&1)*4)*4;
    uint32_t Vln = vBase + ((((mid&1)*8 + l7)*PW) + (mid>>1)*4)*4;

    // load Q tile (128x64 halves) via uint4 copies
    #pragma unroll
    for (int it = 0; it < 8; it++) {
        int u  = tid + it*128;
        int r  = u >> 3;
        int cu = u & 7;
        uint4 v = *(const uint4*)&qptr[(size_t)(q0 + r)*HD + cu*8];
        *(uint4*)&Qs[r][cu*4] = v;
    }

    // prefetch K/V tiles 0,1 into stages 0,1
    #pragma unroll
    for (int s = 0; s < ASTG-1; s++) {
        #pragma unroll
        for (int it = 0; it < 4; it++) {
            int r = s*KT + sr + it*16;
            CPA16(sK0 + s*KVSTGB + it*16*PW*4, &kptr[(size_t)r*HD + scu*8]);
            CPA16(sV0 + s*KVSTGB + it*16*PW*4, &vptr[(size_t)r*HD + scu*8]);
        }
        CP_COMMIT();
    }

    float m_a[2], m_b[2];
    float Lacc[2][4];           // tensor-core-accumulated row sums
    float O[2][8][4];
    #pragma unroll
    for (int mt = 0; mt < 2; mt++) {
        m_a[mt] = -INFINITY; m_b[mt] = -INFINITY;
        #pragma unroll
        for (int e = 0; e < 4; e++) Lacc[mt][e] = 0.f;
        #pragma unroll
        for (int dt = 0; dt < 8; dt++)
            #pragma unroll
            for (int e = 0; e < 4; e++) O[mt][dt][e] = 0.f;
    }

    const uint32_t bf_ones[2] = { ONES_H2, ONES_H2 };

    const int NTI = SEQ/KT;   // 32
    for (int ti = 0; ti < NTI; ti++) {
        if (ti + 1 < NTI) CP_WAIT1();
        else              CP_WAIT0();
        __syncthreads();

        int sl = ti % ASTG;
        uint32_t Klb = Kln + sl*KVSTGB;
        uint32_t Vlb = Vln + sl*KVSTGB;

        // S = Q @ K^T
        float S[2][8][4];
        #pragma unroll
        for (int mt = 0; mt < 2; mt++)
            #pragma unroll
            for (int nt = 0; nt < 8; nt++)
                #pragma unroll
                for (int e = 0; e < 4; e++) S[mt][nt][e] = 0.f;

        #pragma unroll
        for (int kk = 0; kk < 4; kk++) {
            uint32_t bf[8][2];
            #pragma unroll
            for (int ntp = 0; ntp < 4; ntp++)
                LDSM4(bf[2*ntp][0], bf[2*ntp][1], bf[2*ntp+1][0], bf[2*ntp+1][1],
                      Klb + (ntp*16*PW + kk*8)*4);
            #pragma unroll
            for (int mt = 0; mt < 2; mt++) {
                uint32_t qf[4];
                LDSM4(qf[0], qf[1], qf[2], qf[3],
                      Qln + (mt*16*PW + kk*8)*4);
                #pragma unroll
                for (int nt = 0; nt < 8; nt++)
                    mma_f16(S[mt][nt], qf, bf[nt]);
            }
        }

        // prefetch tile ti+2
        int nt2 = ti + ASTG - 1;
        if (nt2 < NTI) {
            int ps = nt2 % ASTG;
            #pragma unroll
            for (int it = 0; it < 4; it++) {
                int r = nt2*KT + sr + it*16;
                CPA16(sK0 + ps*KVSTGB + it*16*PW*4, &kptr[(size_t)r*HD + scu*8]);
                CPA16(sV0 + ps*KVSTGB + it*16*PW*4, &vptr[(size_t)r*HD + scu*8]);
            }
            CP_COMMIT();
        }

        // online softmax: max reduction + packed-half exp2; P overwrites S.
        #pragma unroll
        for (int mt = 0; mt < 2; mt++) {
            float ma = S[mt][0][0], mb = S[mt][0][2];
            #pragma unroll
            for (int nt = 0; nt < 8; nt++) {
                ma = fmaxf(ma, fmaxf(S[mt][nt][0], S[mt][nt][1]));
                mb = fmaxf(mb, fmaxf(S[mt][nt][2], S[mt][nt][3]));
            }
            #pragma unroll
            for (int off = 1; off <= 2; off <<= 1) {
                ma = fmaxf(ma, __shfl_xor_sync(0xffffffffu, ma, off));
                mb = fmaxf(mb, __shfl_xor_sync(0xffffffffu, mb, off));
            }
            float mna = fmaxf(m_a[mt], ma);
            float mnb = fmaxf(m_b[mt], mb);
            float alpha_a = ex2f(m_a[mt] - mna);
            float alpha_b = ex2f(m_b[mt] - mnb);
            m_a[mt] = mna; m_b[mt] = mnb;

            #pragma unroll
            for (int nt = 0; nt < 8; nt++) {
                // subtract in fp32, pack, packed exp2 -> P as half2 word
                uint32_t pa = f2h2(S[mt][nt][0] - mna, S[mt][nt][1] - mna);
                uint32_t pb = f2h2(S[mt][nt][2] - mnb, S[mt][nt][3] - mnb);
                S[mt][nt][0] = __uint_as_float(ex2h2(pa));
                S[mt][nt][2] = __uint_as_float(ex2h2(pb));
            }

            Lacc[mt][0] *= alpha_a; Lacc[mt][1] *= alpha_a;
            Lacc[mt][2] *= alpha_b; Lacc[mt][3] *= alpha_b;
            #pragma unroll
            for (int dt = 0; dt < 8; dt++) {
                O[mt][dt][0] *= alpha_a; O[mt][dt][1] *= alpha_a;
                O[mt][dt][2] *= alpha_b; O[mt][dt][3] *= alpha_b;
            }
        }

        // O += P @ V ; l += P @ 1  (both on the tensor core)
        #pragma unroll
        for (int kk = 0; kk < 4; kk++) {
            uint32_t bv[8][2];
            #pragma unroll
            for (int dtp = 0; dtp < 4; dtp++)
                LDSM4T(bv[2*dtp][0], bv[2*dtp][1], bv[2*dtp+1][0], bv[2*dtp+1][1],
                       Vlb + (kk*16*PW + dtp*8)*4);
            #pragma unroll
            for (int mt = 0; mt < 2; mt++) {
                uint32_t af[4];
                af[0] = __float_as_uint(S[mt][2*kk][0]);
                af[1] = __float_as_uint(S[mt][2*kk][2]);
                af[2] = __float_as_uint(S[mt][2*kk+1][0]);
                af[3] = __float_as_uint(S[mt][2*kk+1][2]);
                #pragma unroll
                for (int dt = 0; dt < 8; dt++)
                    mma_f16(O[mt][dt], af, bv[dt]);
                mma_f16(Lacc[mt], af, bf_ones);
            }
        }
    }

    // write normalized output as fp16 (B,S,D)
    int gid = lane >> 2, q4 = lane & 3;
    #pragma unroll
    for (int mt = 0; mt < 2; mt++) {
        float inv_a = 1.f / Lacc[mt][0];
        float inv_b = 1.f / Lacc[mt][2];
        int rr = w*32 + mt*16 + gid;
        size_t base_a = ((size_t)b*SEQ + q0 + rr)*DIM + h*HD;
        size_t base_b = ((size_t)b*SEQ + q0 + rr + 8)*DIM + h*HD;
        #pragma unroll
        for (int dt = 0; dt < 8; dt++) {
            int col = dt*8 + 2*q4;
            *(uint32_t*)&g_attn[base_a + col] =
                f2h2(O[mt][dt][0]*inv_a, O[mt][dt][1]*inv_a);
            *(uint32_t*)&g_attn[base_b + col] =
                f2h2(O[mt][dt][2]*inv_b, O[mt][dt][3]*inv_b);
        }
    }
}

// ---------------------------------------------------------------------------
extern "C" void kernel_launch(void* const* d_in, const int* in_sizes, int n_in,
                              void* d_out, int out_size)
{
    const float* x      = (const float*)d_in[0];
    const float* w_qkv  = (const float*)d_in[1];
    const float* b_qkv  = (const float*)d_in[2];
    const float* w_out  = (const float*)d_in[3];
    const float* b_out  = (const float*)d_in[4];
    float* out = (float*)d_out;

    __half* xh_p;    cudaGetSymbolAddress((void**)&xh_p,    g_xh);
    __half* wqkvT_p; cudaGetSymbolAddress((void**)&wqkvT_p, g_wqkvT);
    __half* woutT_p; cudaGetSymbolAddress((void**)&woutT_p, g_woutT);

    // 0) prep: x -> fp16, weight transpose + fp16 convert
    xcvt<<<MTOK*DIM/4/256, 256>>>(x, xh_p);
    wtrans<<<dim3(3*DIM/32, DIM/32), dim3(32,8)>>>(w_qkv, wqkvT_p, DIM, 3*DIM);
    wtrans<<<dim3(DIM/32,   DIM/32), dim3(32,8)>>>(w_out, woutT_p, DIM, DIM);

    // 1) QKV projection + scatter (round-12 exact GEMM)
    cudaFuncSetAttribute(gemm_qkv,
        cudaFuncAttributeMaxDynamicSharedMemorySize, GEMM_SMEM);
    dim3 g1(3*DIM/128, MTOK/128);
    gemm_qkv<<<g1, 256, GEMM_SMEM>>>(b_qkv);

    // 2) fused attention (tensor-core l, packed-half exp2)
    size_t asmem = (size_t)ATT_SMEM_WORDS * sizeof(uint32_t);  // 73728 B
    cudaFuncSetAttribute(attn_kernel,
        cudaFuncAttributeMaxDynamicSharedMemorySize, (int)asmem);
    dim3 g2(SEQ/QT, NH, BATCH);
    attn_kernel<<<g2, 128, asmem>>>();

    // 3) output projection (round-12 exact GEMM)
    cudaFuncSetAttribute(gemm_out,
        cudaFuncAttributeMaxDynamicSharedMemorySize, GEMM_SMEM);
    dim3 g3(DIM/128, MTOK/128);
    gemm_out<<<g3, 256, GEMM_SMEM>>>(b_out, out);
}